// round 14
// baseline (speedup 1.0000x reference)
#include <cuda_runtime.h>
#include <cuda_bf16.h>
#include <stdint.h>
#include <math.h>

#define BQ 4
#define NP 8192
#define SP 512
#define KNN 16
#define FD 128
#define EPSV 1e-5f
typedef unsigned long long u64;

__device__ float g_feats[BQ*NP*FD];
__device__ float g_q[BQ*NP*FD];
__device__ int   g_fps[BQ*SP];
__device__ int   g_idx_dn[BQ*SP*KNN];
__device__ float g_new_xyz[BQ*SP*3];
__device__ float g_new_xyzp[BQ*SP*4];
__device__ float g_h0[BQ*SP*KNN*FD];
__device__ float g_h1[BQ*SP*KNN*FD];
__device__ float g_part[64*2*FD];
__device__ float g_m0[FD]; __device__ float g_v0[FD];
__device__ float g_m1[FD]; __device__ float g_v1[FD];
__device__ float g_newfeat[BQ*SP*FD];
__device__ float g_newx[BQ*SP*FD];
__device__ float g_ktab[BQ*SP*FD];
__device__ float g_vtab[BQ*SP*FD];
__device__ int   g_idx_up[BQ*NP*KNN];
__device__ float g_pe[67108864];
__device__ float g_res[BQ*NP*FD];
__device__ float g_wqc[FD*FD];
__device__ float g_bqc[FD];

// ---- f32x2 helpers ----
__device__ __forceinline__ u64 pk2(float a){ u64 r; asm("mov.b64 %0,{%1,%1};" : "=l"(r) : "f"(a)); return r; }
__device__ __forceinline__ void fma2(u64& d, u64 a, u64 b){ asm("fma.rn.f32x2 %0,%1,%2,%0;" : "+l"(d) : "l"(a), "l"(b)); }
__device__ __forceinline__ void upk(u64 v, float& lo, float& hi){ asm("mov.b64 {%0,%1},%2;" : "=f"(lo), "=f"(hi) : "l"(v)); }

__device__ __forceinline__ void gemm32_core(const float* __restrict__ Wsh, const float* __restrict__ Ash,
                                            int kg, int cg, u64 acc[8][2]){
    #pragma unroll
    for (int r=0;r<8;r++){ acc[r][0]=0ull; acc[r][1]=0ull; }
    const float* arow = Ash + (kg<<3)*FD;
    #pragma unroll 4
    for (int i=0;i<FD;i++){
        ulonglong2 w = *(const ulonglong2*)(Wsh + i*FD + (cg<<2));
        #pragma unroll
        for (int r=0;r<8;r++){
            u64 a2 = pk2(arow[r*FD + i]);
            fma2(acc[r][0], a2, w.x);
            fma2(acc[r][1], a2, w.y);
        }
    }
}

// ---- mma.sync helpers ----
__device__ __forceinline__ uint32_t smem_u32(const void* p){
    uint32_t a; asm("{ .reg .u64 t; cvta.to.shared.u64 t, %1; cvt.u32.u64 %0, t; }" : "=r"(a) : "l"(p)); return a;
}
#define LDSM4(r, addr) \
    asm volatile("ldmatrix.sync.aligned.m8n8.x4.shared.b16 {%0,%1,%2,%3}, [%4];" \
        : "=r"((r)[0]),"=r"((r)[1]),"=r"((r)[2]),"=r"((r)[3]) : "r"(addr))
#define MMA16816(cc, a, b0, b1) \
    asm volatile("mma.sync.aligned.m16n8k16.row.col.f32.bf16.bf16.f32 " \
        "{%0,%1,%2,%3},{%4,%5,%6,%7},{%8,%9},{%0,%1,%2,%3};" \
        : "+f"((cc)[0]),"+f"((cc)[1]),"+f"((cc)[2]),"+f"((cc)[3]) \
        : "r"((a)[0]),"r"((a)[1]),"r"((a)[2]),"r"((a)[3]),"r"(b0),"r"(b1))
__device__ __forceinline__ void bfsplit(float v, __nv_bfloat16& h, __nv_bfloat16& l){
    h=__float2bfloat16_rn(v); l=__float2bfloat16_rn(v-__bfloat162float(h));
}

__device__ __forceinline__ void wgemm(uint32_t aH, uint32_t aL, uint32_t bH, uint32_t bL,
                                      int wr, int wc, uint32_t offA, uint32_t offB, float c[32]){
    #pragma unroll
    for (int i=0;i<32;i++) c[i]=0.f;
    #pragma unroll
    for (int ks=0;ks<8;ks++){
        uint32_t k2 = ks*32;
        uint32_t ah[2][4], al[2][4], bh[2][4], bl[2][4];
        #pragma unroll
        for (int mt=0;mt<2;mt++){
            uint32_t ra = (uint32_t)(32*wr+16*mt)*272u + k2 + offA;
            LDSM4(ah[mt], aH + ra);
            LDSM4(al[mt], aL + ra);
        }
        #pragma unroll
        for (int np=0;np<2;np++){
            uint32_t rb = (uint32_t)(32*wc+16*np)*272u + k2 + offB;
            LDSM4(bh[np], bH + rb);
            LDSM4(bl[np], bL + rb);
        }
        #pragma unroll
        for (int mt=0;mt<2;mt++){
            #pragma unroll
            for (int nt=0;nt<4;nt++){
                float* cc = c + (mt*4+nt)*4;
                uint32_t b0h=bh[nt>>1][(nt&1)*2], b1h=bh[nt>>1][(nt&1)*2+1];
                uint32_t b0l=bl[nt>>1][(nt&1)*2], b1l=bl[nt>>1][(nt&1)*2+1];
                MMA16816(cc, ah[mt], b0h, b1h);
                MMA16816(cc, ah[mt], b0l, b1l);
                MMA16816(cc, al[mt], b0h, b1h);
            }
        }
    }
}

// ---------------- layernorm ----------------
__global__ void k_layernorm(const float* __restrict__ x, const float* __restrict__ g,
                            const float* __restrict__ b, float* __restrict__ out){
    int row = blockIdx.x, t = threadIdx.x;
    __shared__ float sh[8];
    float v = x[(size_t)row*FD + t];
    float s = v;
    #pragma unroll
    for (int o=16;o;o>>=1) s += __shfl_xor_sync(0xffffffffu, s, o);
    if ((t&31)==0) sh[t>>5]=s;
    __syncthreads();
    float mean = (sh[0]+sh[1]+sh[2]+sh[3]) * (1.0f/FD);
    float d = v - mean;
    float s2 = d*d;
    #pragma unroll
    for (int o=16;o;o>>=1) s2 += __shfl_xor_sync(0xffffffffu, s2, o);
    if ((t&31)==0) sh[4+(t>>5)]=s2;
    __syncthreads();
    float var = (sh[4]+sh[5]+sh[6]+sh[7]) * (1.0f/FD);
    out[(size_t)row*FD+t] = d * rsqrtf(var + EPSV) * g[t] + b[t];
}

// ---------------- FPS (single-barrier-pair all-warp reduction) ----------------
__global__ void k_fps(const float* __restrict__ xyzp){
    extern __shared__ float sm[];
    float* xs = sm; float* ys = sm + NP; float* zs = sm + 2*NP;
    int b = blockIdx.x, t = threadIdx.x, lane = t&31, w = t>>5;
    float px[8], py[8], pz[8], md[8];
    #pragma unroll
    for (int j=0;j<8;j++){
        int i = t + j*1024;
        float4 p = ((const float4*)xyzp)[(size_t)b*NP + i];
        px[j]=p.x; py[j]=p.y; pz[j]=p.z; md[j]=1e10f;
        xs[i]=p.x; ys[i]=p.y; zs[i]=p.z;
    }
    __shared__ u64 warpbest[32];
    if (t==0) g_fps[b*SP]=0;
    __syncthreads();
    int last = 0;
    for (int s=1;s<SP;s++){
        float lx=xs[last], ly=ys[last], lz=zs[last];
        u64 best=0;
        #pragma unroll
        for (int j=0;j<8;j++){
            float dx=px[j]-lx, dy=py[j]-ly, dz=pz[j]-lz;
            float d = dx*dx+dy*dy+dz*dz;
            md[j] = fminf(md[j], d);
            u64 key = ((u64)__float_as_uint(md[j])<<32) | (unsigned)(NP-1 - (t + j*1024));
            best = key > best ? key : best;
        }
        #pragma unroll
        for (int o=16;o;o>>=1){
            u64 oth = __shfl_xor_sync(0xffffffffu, best, o);
            best = oth > best ? oth : best;
        }
        if (lane==0) warpbest[w]=best;
        __syncthreads();
        u64 bb = warpbest[lane];
        #pragma unroll
        for (int o=16;o;o>>=1){
            u64 oth = __shfl_xor_sync(0xffffffffu, bb, o);
            bb = oth > bb ? oth : bb;
        }
        last = NP-1 - (int)(bb & 0xffffffffu);
        if (t==0) g_fps[b*SP+s]=last;
        __syncthreads();
    }
}

// ---------------- knn_dn (incremental local-min selection) ----------------
__global__ void k_knn_dn(const float* __restrict__ xyzp){
    extern __shared__ float sm[];
    float* xs = sm; float* ys = sm+NP; float* zs = sm+2*NP;
    int b = blockIdx.x >> 5, blk = blockIdx.x & 31;
    int t = threadIdx.x, w = t>>5, lane = t&31;
    for (int i=t;i<NP;i+=256){
        float4 p = ((const float4*)xyzp)[(size_t)b*NP + i];
        xs[i]=p.x; ys[i]=p.y; zs[i]=p.z;
    }
    __syncthreads();
    for (int qi=0; qi<2; qi++){
        int s = blk*16 + w*2 + qi;
        int qidx = g_fps[b*SP+s];
        float qx=xs[qidx], qy=ys[qidx], qz=zs[qidx];
        if (lane==0){
            g_new_xyz[(b*SP+s)*3+0]=qx; g_new_xyz[(b*SP+s)*3+1]=qy; g_new_xyz[(b*SP+s)*3+2]=qz;
        }
        u64 kk[16];
        #pragma unroll
        for (int j=0;j<16;j++) kk[j]=~0ull;
        for (int r=lane; r<NP; r+=32){
            float dx=xs[r]-qx, dy=ys[r]-qy, dz=zs[r]-qz;
            float d = dx*dx+dy*dy+dz*dz;
            u64 key = ((u64)__float_as_uint(d)<<32) | (unsigned)r;
            if (key < kk[15]){
                #pragma unroll
                for (int j=0;j<16;j++){
                    u64 lo = kk[j] < key ? kk[j] : key;
                    u64 hi = kk[j] < key ? key : kk[j];
                    kk[j]=lo; key=hi;
                }
            }
        }
        u64 lmin=~0ull;
        #pragma unroll
        for (int j=0;j<16;j++) lmin = kk[j]<lmin ? kk[j] : lmin;
        for (int r=0;r<16;r++){
            u64 g=lmin;
            #pragma unroll
            for (int o=16;o;o>>=1){
                u64 oth=__shfl_xor_sync(0xffffffffu,g,o);
                g = oth<g ? oth : g;
            }
            if (lane==0){
                int id=(int)(g & 0xffffffffu);
                g_idx_dn[(b*SP+s)*KNN + r]=id;
                if (r==0) ((float4*)g_new_xyzp)[b*SP+s] = ((const float4*)xyzp)[(size_t)b*NP + id];
            }
            if (lmin==g){
                u64 thr=g+1ull, nm=~0ull;
                #pragma unroll
                for (int j=0;j<16;j++){ u64 v=kk[j]; if (v>=thr && v<nm) nm=v; }
                lmin=nm;
            }
        }
    }
}

// ---------------- knn_up (incremental local-min selection) ----------------
__global__ void k_knn_up(const float* __restrict__ xyzp){
    __shared__ float rx[SP], ry[SP], rz[SP];
    int t=threadIdx.x, w=t>>5, lane=t&31;
    int b = blockIdx.x >> 10;
    int n = (blockIdx.x & 1023)*8 + w;
    for (int i=t;i<SP;i+=256){
        rx[i]=g_new_xyz[(i+b*SP)*3+0]; ry[i]=g_new_xyz[(i+b*SP)*3+1]; rz[i]=g_new_xyz[(i+b*SP)*3+2];
    }
    __syncthreads();
    float4 qp = ((const float4*)xyzp)[(size_t)b*NP + n];
    u64 kk[16];
    u64 lmin=~0ull;
    #pragma unroll
    for (int j=0;j<16;j++){
        int r = lane + 32*j;
        float dx=rx[r]-qp.x, dy=ry[r]-qp.y, dz=rz[r]-qp.z;
        kk[j] = ((u64)__float_as_uint(dx*dx+dy*dy+dz*dz)<<32) | (unsigned)r;
        lmin = kk[j]<lmin ? kk[j] : lmin;
    }
    for (int r=0;r<16;r++){
        u64 g=lmin;
        #pragma unroll
        for (int o=16;o;o>>=1){
            u64 oth=__shfl_xor_sync(0xffffffffu,g,o);
            g = oth<g ? oth : g;
        }
        if (lane==0) g_idx_up[((size_t)b*NP+n)*KNN + r] = (int)(g & 0xffffffffu);
        if (lmin==g){
            u64 thr=g+1ull, nm=~0ull;
            #pragma unroll
            for (int j=0;j<16;j++){ u64 v=kk[j]; if (v>=thr && v<nm) nm=v; }
            lmin=nm;
        }
    }
}

// ---------------- h0 ----------------
__global__ __launch_bounds__(128) void k_h032(const float* __restrict__ xyzp,
                                              const float* __restrict__ tw0,
                                              const float* __restrict__ tb0){
    extern __shared__ float sm[];
    float* Wsh = sm;
    float* Ash = sm + 16384;
    __shared__ float w3[3*FD];
    __shared__ float gx[32][3];
    __shared__ int idxs[32];
    int t = threadIdx.x, bs = blockIdx.x;
    int s0 = bs*2, b = s0 >> 9;
    for (int i=t;i<16384;i+=128) Wsh[i] = tw0[384 + i];
    w3[t]=tw0[t]; w3[128+t]=tw0[128+t]; w3[256+t]=tw0[256+t];
    if (t<32){
        int s = s0 + (t>>4);
        int id = g_idx_dn[s*KNN + (t&15)];
        idxs[t]=id;
        gx[t][0]=xyzp[((size_t)b*NP+id)*4+0]-g_new_xyz[s*3+0];
        gx[t][1]=xyzp[((size_t)b*NP+id)*4+1]-g_new_xyz[s*3+1];
        gx[t][2]=xyzp[((size_t)b*NP+id)*4+2]-g_new_xyz[s*3+2];
    }
    __syncthreads();
    #pragma unroll
    for (int k=0;k<32;k++) Ash[k*FD+t] = g_feats[((size_t)b*NP+idxs[k])*FD + t];
    __syncthreads();
    int kg=t>>5, cg=t&31;
    u64 acc[8][2];
    gemm32_core(Wsh, Ash, kg, cg, acc);
    float4 bv = ((const float4*)tb0)[cg];
    #pragma unroll
    for (int r=0;r<8;r++){
        int row = (kg<<3)+r;
        float g0=gx[row][0], g1=gx[row][1], g2=gx[row][2];
        float c0,c1,c2,c3;
        upk(acc[r][0],c0,c1); upk(acc[r][1],c2,c3);
        int cb=cg<<2;
        c0 += bv.x + g0*w3[cb+0] + g1*w3[128+cb+0] + g2*w3[256+cb+0];
        c1 += bv.y + g0*w3[cb+1] + g1*w3[128+cb+1] + g2*w3[256+cb+1];
        c2 += bv.z + g0*w3[cb+2] + g1*w3[128+cb+2] + g2*w3[256+cb+2];
        c3 += bv.w + g0*w3[cb+3] + g1*w3[128+cb+3] + g2*w3[256+cb+3];
        ((float4*)g_h0)[((size_t)bs*32 + row)*32 + cg] = make_float4(c0,c1,c2,c3);
    }
}

// ---------------- stats ----------------
__global__ void k_stats_part(const float* __restrict__ X, int nrows, float* __restrict__ part){
    int t=threadIdx.x, blk=blockIdx.x;
    int chunk = nrows/64;
    float s=0.f, s2=0.f;
    for (int r=0;r<chunk;r++){
        float v = X[((size_t)(blk*chunk+r))*FD + t];
        s += v; s2 += v*v;
    }
    part[blk*2*FD + t] = s;
    part[blk*2*FD + FD + t] = s2;
}
__global__ void k_stats_final(const float* __restrict__ part, int nrows,
                              float* __restrict__ mean, float* __restrict__ var){
    int t=threadIdx.x;
    float s=0.f, s2=0.f;
    for (int i=0;i<64;i++){ s += part[i*2*FD+t]; s2 += part[i*2*FD+FD+t]; }
    float m = s/(float)nrows;
    mean[t]=m;
    var[t]=s2/(float)nrows - m*m;
}

// ---------------- gemm128 ----------------
__global__ __launch_bounds__(128) void k_gemm128(
        const float* __restrict__ A, const float* __restrict__ W,
        const float* __restrict__ bias, float* __restrict__ C, int flags,
        const float* __restrict__ bnm, const float* __restrict__ bnv,
        const float* __restrict__ bng, const float* __restrict__ bnb,
        const float* __restrict__ addsrc){
    extern __shared__ float sm[];
    float* Wsh = sm; float* Ash = sm + 16384;
    int t=threadIdx.x;
    size_t row0 = (size_t)blockIdx.x*32;
    for (int i=t;i<4096;i+=128) ((float4*)Wsh)[i]=((const float4*)W)[i];
    float bm=0.f, brv=1.f, bg=1.f, bb=0.f;
    if (flags&2){ bm=bnm[t]; brv=rsqrtf(bnv[t]+EPSV); bg=bng[t]; bb=bnb[t]; }
    #pragma unroll
    for (int k=0;k<32;k++){
        float v = A[(row0+k)*FD + t];
        if (flags&2) v = fmaxf((v-bm)*brv*bg + bb, 0.f);
        Ash[k*FD+t]=v;
    }
    __syncthreads();
    int kg=t>>5, cg=t&31;
    u64 acc[8][2];
    gemm32_core(Wsh, Ash, kg, cg, acc);
    float4 bv = bias ? ((const float4*)bias)[cg] : make_float4(0.f,0.f,0.f,0.f);
    #pragma unroll
    for (int r=0;r<8;r++){
        size_t row = row0 + (kg<<3) + r;
        float c0,c1,c2,c3;
        upk(acc[r][0],c0,c1); upk(acc[r][1],c2,c3);
        float4 o = make_float4(c0+bv.x, c1+bv.y, c2+bv.z, c3+bv.w);
        if (flags&1){ o.x=fmaxf(o.x,0.f); o.y=fmaxf(o.y,0.f); o.z=fmaxf(o.z,0.f); o.w=fmaxf(o.w,0.f); }
        if (flags&4){
            float4 ad = ((const float4*)addsrc)[row*32 + cg];
            o.x+=ad.x; o.y+=ad.y; o.z+=ad.z; o.w+=ad.w;
        }
        ((float4*)C)[row*32 + cg] = o;
    }
}

// ---------------- maxpool / foldb ----------------
__global__ void k_maxpool(const float* __restrict__ bg, const float* __restrict__ bb){
    int bs = blockIdx.x, t = threadIdx.x;
    float m = g_m1[t], rv = rsqrtf(g_v1[t]+EPSV), ga=bg[t], be=bb[t];
    float best = -1e30f;
    #pragma unroll
    for (int k=0;k<KNN;k++){
        float v = g_h1[((size_t)bs*KNN+k)*FD + t];
        v = fmaxf((v-m)*rv*ga + be, 0.f);
        best = fmaxf(best, v);
    }
    g_newfeat[(size_t)bs*FD+t] = best;
}
__global__ void k_foldb(const float* __restrict__ bk, const float* __restrict__ wq){
    int t = threadIdx.x;
    float s = 0.f;
    for (int i=0;i<FD;i++) s += bk[i]*wq[i*FD+t];
    g_bqc[t] = s;
}

// ================= posenc via mma.sync split-bf16 (validated R12) =================
#define PM_PD  0
#define PM_B2  1024
#define PM_AHI 1536
#define PM_ALO 18944
#define PM_WH  36352
#define PM_WL  71168
#define PM_SZ  105984
__global__ __launch_bounds__(256,2) void k_posenc_mma(
        const float* __restrict__ xyzp,
        const float* __restrict__ pe_w1, const float* __restrict__ pe_b1,
        const float* __restrict__ pe_w2, const float* __restrict__ pe_b2){
    extern __shared__ __align__(1024) char smem[];
    uint32_t sb = smem_u32(smem);
    int t=threadIdx.x, wid=t>>5, lane=t&31;
    float* pd =(float*)(smem+PM_PD);
    float* b2s=(float*)(smem+PM_B2);
    if (t<128) b2s[t]=pe_b2[t];
    for (int j=t;j<16384;j+=256){
        int k=j>>7, n=j&127;
        uint32_t off=(uint32_t)n*272u + (uint32_t)k*2u;
        __nv_bfloat16 h,l; bfsplit(pe_w2[k*128+n],h,l);
        *(__nv_bfloat16*)(smem+PM_WH+off)=h;
        *(__nv_bfloat16*)(smem+PM_WL+off)=l;
    }
    int c=t&127, rh=t>>7;
    float w0=pe_w1[c], w1=pe_w1[FD+c], w2=pe_w1[2*FD+c], w3=pe_w1[3*FD+c], bb1=pe_b1[c];
    int wr=wid&1, wc=wid>>1;
    int g=lane>>2, tig=lane&3, r8=lane&7, sel=lane>>3;
    uint32_t offA=(uint32_t)(r8+((sel&1)<<3))*272u + (uint32_t)((sel>>1)<<4);
    uint32_t offB=(uint32_t)(r8+((sel>>1)<<3))*272u + (uint32_t)((sel&1)<<4);
    __syncthreads();
    for (int tp=blockIdx.x; tp<BQ*NP/4; tp+=gridDim.x){
        int bn0=tp*4, b=bn0>>13;
        __syncthreads();
        if (t<64){
            int k=t, bn=bn0+(k>>4);
            int id=g_idx_up[(size_t)bn*KNN+(k&15)];
            float4 qp=((const float4*)xyzp)[bn];
            float4 np=((const float4*)g_new_xyzp)[b*SP+id];
            pd[k*4+0]=qp.x-np.x; pd[k*4+1]=qp.y-np.y; pd[k*4+2]=qp.z-np.z; pd[k*4+3]=qp.w-np.w;
        }
        __syncthreads();
        #pragma unroll 4
        for (int rr=0;rr<32;rr++){
            int r=rh*32+rr;
            float v=fmaxf(bb1 + pd[r*4+0]*w0 + pd[r*4+1]*w1 + pd[r*4+2]*w2 + pd[r*4+3]*w3, 0.f);
            __nv_bfloat16 h,l; bfsplit(v,h,l);
            uint32_t off=(uint32_t)r*272u + (uint32_t)c*2u;
            *(__nv_bfloat16*)(smem+PM_AHI+off)=h;
            *(__nv_bfloat16*)(smem+PM_ALO+off)=l;
        }
        __syncthreads();
        float cfr[32];
        wgemm(sb+PM_AHI, sb+PM_ALO, sb+PM_WH, sb+PM_WL, wr, wc, offA, offB, cfr);
        size_t base=(size_t)bn0*16;
        #pragma unroll
        for (int mt=0;mt<2;mt++){
            #pragma unroll
            for (int nt=0;nt<4;nt++){
                float* cc=cfr+(mt*4+nt)*4;
                int row0=32*wr+16*mt+g;
                int col0=32*wc+8*nt+2*tig;
                float bx=b2s[col0], by=b2s[col0+1];
                *(float2*)(g_pe+(base+row0)*FD+col0)   = make_float2(cc[0]+bx, cc[1]+by);
                *(float2*)(g_pe+(base+row0+8)*FD+col0) = make_float2(cc[2]+bx, cc[3]+by);
            }
        }
    }
}

// ================= att12 via mma.sync split-bf16 (validated R12 form) =================
#define MA_AHI 1280
#define MA_ALO 18688
#define MA_W1H 36096
#define MA_W1L 70912
#define MA_W2H 105728
#define MA_W2L 140544
#define MA_SZ  175360
__global__ __launch_bounds__(256,1) void k_att12_mma(
        const float* __restrict__ at_b1, const float* __restrict__ at_b2,
        const float* __restrict__ at_w1, const float* __restrict__ at_w2){
    extern __shared__ __align__(1024) char smem[];
    uint32_t sb = smem_u32(smem);
    int t=threadIdx.x, wid=t>>5, lane=t&31;
    int*   sidx=(int*)(smem+0);
    float* b1s =(float*)(smem+256);
    float* b2s =(float*)(smem+768);
    float* sfb =(float*)(smem+MA_AHI);
    if (t<128){ b1s[t]=at_b1[t]; b2s[t]=at_b2[t]; }
    for (int j=t;j<16384;j+=256){
        int k=j>>7, n=j&127;
        uint32_t off=(uint32_t)n*272u + (uint32_t)k*2u;
        __nv_bfloat16 h,l;
        bfsplit(at_w1[k*128+n],h,l);
        *(__nv_bfloat16*)(smem+MA_W1H+off)=h; *(__nv_bfloat16*)(smem+MA_W1L+off)=l;
        bfsplit(at_w2[k*128+n],h,l);
        *(__nv_bfloat16*)(smem+MA_W2H+off)=h; *(__nv_bfloat16*)(smem+MA_W2L+off)=l;
    }
    int c=t&127, rh=t>>7;
    int wr=wid&1, wc=wid>>1;
    int g=lane>>2, tig=lane&3, r8=lane&7, sel=lane>>3;
    uint32_t offA=(uint32_t)(r8+((sel&1)<<3))*272u + (uint32_t)((sel>>1)<<4);
    uint32_t offB=(uint32_t)(r8+((sel>>1)<<3))*272u + (uint32_t)((sel&1)<<4);
    const float inv = 0.08838834764831845f;
    __syncthreads();
    for (int tp=blockIdx.x; tp<BQ*NP/4; tp+=gridDim.x){
        int bn0=tp*4, b=bn0>>13;
        __syncthreads();
        if (t<64) sidx[t]=g_idx_up[(size_t)(bn0+(t>>4))*KNN + (t&15)];
        __syncthreads();
        {
            float qs[4];
            #pragma unroll
            for (int p=0;p<4;p++) qs[p]=g_q[(size_t)(bn0+p)*FD+c];
            #pragma unroll 4
            for (int rr=0;rr<32;rr++){
                int r=rh*32+rr;
                int id=sidx[r];
                float v=qs[r>>4]-g_ktab[(size_t)(b*SP+id)*FD+c]+g_pe[((size_t)bn0*16+r)*FD+c];
                __nv_bfloat16 h,l; bfsplit(v,h,l);
                uint32_t off=(uint32_t)r*272u + (uint32_t)c*2u;
                *(__nv_bfloat16*)(smem+MA_AHI+off)=h;
                *(__nv_bfloat16*)(smem+MA_ALO+off)=l;
            }
        }
        __syncthreads();
        float cfr[32];
        wgemm(sb+MA_AHI, sb+MA_ALO, sb+MA_W1H, sb+MA_W1L, wr, wc, offA, offB, cfr);
        __syncthreads();
        #pragma unroll
        for (int mt=0;mt<2;mt++){
            #pragma unroll
            for (int nt=0;nt<4;nt++){
                float* cc=cfr+(mt*4+nt)*4;
                int row0=32*wr+16*mt+g;
                int col0=32*wc+8*nt+2*tig;
                float bvx=b1s[col0], bvy=b1s[col0+1];
                float v0=fmaxf(cc[0]+bvx,0.f), v1=fmaxf(cc[1]+bvy,0.f);
                float v2=fmaxf(cc[2]+bvx,0.f), v3=fmaxf(cc[3]+bvy,0.f);
                __nv_bfloat16 h0,l0,h1,l1;
                uint32_t o0=(uint32_t)row0*272u+(uint32_t)col0*2u;
                uint32_t o1=(uint32_t)(row0+8)*272u+(uint32_t)col0*2u;
                __nv_bfloat162 hp,lp;
                bfsplit(v0,h0,l0); bfsplit(v1,h1,l1);
                hp.x=h0; hp.y=h1; lp.x=l0; lp.y=l1;
                *(__nv_bfloat162*)(smem+MA_AHI+o0)=hp; *(__nv_bfloat162*)(smem+MA_ALO+o0)=lp;
                bfsplit(v2,h0,l0); bfsplit(v3,h1,l1);
                hp.x=h0; hp.y=h1; lp.x=l0; lp.y=l1;
                *(__nv_bfloat162*)(smem+MA_AHI+o1)=hp; *(__nv_bfloat162*)(smem+MA_ALO+o1)=lp;
            }
        }
        __syncthreads();
        wgemm(sb+MA_AHI, sb+MA_ALO, sb+MA_W2H, sb+MA_W2L, wr, wc, offA, offB, cfr);
        __syncthreads();
        #pragma unroll
        for (int mt=0;mt<2;mt++){
            #pragma unroll
            for (int nt=0;nt<4;nt++){
                float* cc=cfr+(mt*4+nt)*4;
                int row0=32*wr+16*mt+g;
                int col0=32*wc+8*nt+2*tig;
                sfb[col0*66+row0]      =cc[0]+b2s[col0];
                sfb[(col0+1)*66+row0]  =cc[1]+b2s[col0+1];
                sfb[col0*66+row0+8]    =cc[2]+b2s[col0];
                sfb[(col0+1)*66+row0+8]=cc[3]+b2s[col0+1];
            }
        }
        __syncthreads();
        #pragma unroll
        for (int j=0;j<2;j++){
            int item=t+256*j;
            int p=item>>7, ch=item&127;
            float s[16], mx=-1e30f;
            #pragma unroll
            for (int k=0;k<16;k++){ s[k]=sfb[ch*66+p*16+k]*inv; mx=fmaxf(mx,s[k]); }
            float den=0.f;
            #pragma unroll
            for (int k=0;k<16;k++){ s[k]=expf(s[k]-mx); den+=s[k]; }
            float rden=1.f/den, r=0.f;
            #pragma unroll
            for (int k=0;k<16;k++){
                int id=sidx[p*16+k];
                float v=g_vtab[(size_t)(b*SP+id)*FD+ch] + g_pe[((size_t)bn0*16+p*16+k)*FD+ch];
                r += s[k]*rden*v;
            }
            g_res[(size_t)(bn0+p)*FD+ch]=r;
        }
    }
}

extern "C" void kernel_launch(void* const* d_in, const int* in_sizes, int n_in,
                              void* d_out, int out_size){
    const float* xyzp     = (const float*)d_in[0];
    const float* features = (const float*)d_in[1];
    const float* ln_g     = (const float*)d_in[2];
    const float* ln_b     = (const float*)d_in[3];
    const float* td_w0    = (const float*)d_in[4];
    const float* td_b0    = (const float*)d_in[5];
    const float* td_bn0_g = (const float*)d_in[6];
    const float* td_bn0_b = (const float*)d_in[7];
    const float* td_w1    = (const float*)d_in[8];
    const float* td_b1    = (const float*)d_in[9];
    const float* td_bn1_g = (const float*)d_in[10];
    const float* td_bn1_b = (const float*)d_in[11];
    const float* w_kern   = (const float*)d_in[12];
    const float* b_kern   = (const float*)d_in[13];
    const float* w_gkern  = (const float*)d_in[14];
    const float* b_gkern  = (const float*)d_in[15];
    const float* w_agg    = (const float*)d_in[16];
    const float* b_agg    = (const float*)d_in[17];
    const float* w_q      = (const float*)d_in[18];
    const float* w_k      = (const float*)d_in[19];
    const float* w_v      = (const float*)d_in[20];
    const float* pe_w1    = (const float*)d_in[21];
    const float* pe_b1    = (const float*)d_in[22];
    const float* pe_w2    = (const float*)d_in[23];
    const float* pe_b2    = (const float*)d_in[24];
    const float* at_w1    = (const float*)d_in[25];
    const float* at_b1    = (const float*)d_in[26];
    const float* at_w2    = (const float*)d_in[27];
    const float* at_b2    = (const float*)d_in[28];
    float* out = (float*)d_out;

    float *p_feats,*p_q,*p_h0,*p_h1,*p_part,*p_m0,*p_v0,*p_m1,*p_v1;
    float *p_newfeat,*p_newx,*p_ktab,*p_vtab,*p_res,*p_wqc,*p_bqc;
    cudaGetSymbolAddress((void**)&p_feats,   g_feats);
    cudaGetSymbolAddress((void**)&p_q,       g_q);
    cudaGetSymbolAddress((void**)&p_h0,      g_h0);
    cudaGetSymbolAddress((void**)&p_h1,      g_h1);
    cudaGetSymbolAddress((void**)&p_part,    g_part);
    cudaGetSymbolAddress((void**)&p_m0,      g_m0);
    cudaGetSymbolAddress((void**)&p_v0,      g_v0);
    cudaGetSymbolAddress((void**)&p_m1,      g_m1);
    cudaGetSymbolAddress((void**)&p_v1,      g_v1);
    cudaGetSymbolAddress((void**)&p_newfeat, g_newfeat);
    cudaGetSymbolAddress((void**)&p_newx,    g_newx);
    cudaGetSymbolAddress((void**)&p_ktab,    g_ktab);
    cudaGetSymbolAddress((void**)&p_vtab,    g_vtab);
    cudaGetSymbolAddress((void**)&p_res,     g_res);
    cudaGetSymbolAddress((void**)&p_wqc,     g_wqc);
    cudaGetSymbolAddress((void**)&p_bqc,     g_bqc);

    const int SM_PTS  = 3*NP*4;
    const int SM_GEMM = (16384 + 4096)*4;
    cudaFuncSetAttribute(k_fps,        cudaFuncAttributeMaxDynamicSharedMemorySize, SM_PTS);
    cudaFuncSetAttribute(k_knn_dn,     cudaFuncAttributeMaxDynamicSharedMemorySize, SM_PTS);
    cudaFuncSetAttribute(k_h032,       cudaFuncAttributeMaxDynamicSharedMemorySize, SM_GEMM);
    cudaFuncSetAttribute(k_gemm128,    cudaFuncAttributeMaxDynamicSharedMemorySize, SM_GEMM);
    cudaFuncSetAttribute(k_posenc_mma, cudaFuncAttributeMaxDynamicSharedMemorySize, PM_SZ);
    cudaFuncSetAttribute(k_att12_mma,  cudaFuncAttributeMaxDynamicSharedMemorySize, MA_SZ);

    k_layernorm<<<BQ*NP, 128>>>(features, ln_g, ln_b, p_feats);
    k_fps<<<BQ, 1024, SM_PTS>>>(xyzp);
    k_knn_dn<<<BQ*32, 256, SM_PTS>>>(xyzp);
    k_knn_up<<<BQ*1024, 256>>>(xyzp);
    k_h032<<<BQ*SP/2, 128, SM_GEMM>>>(xyzp, td_w0, td_b0);
    k_stats_part<<<64, 128>>>(p_h0, BQ*SP*KNN, p_part);
    k_stats_final<<<1, 128>>>(p_part, BQ*SP*KNN, p_m0, p_v0);
    k_gemm128<<<BQ*SP*KNN/32, 128, SM_GEMM>>>(p_h0, td_w1, td_b1, p_h1, 2,
                                              p_m0, p_v0, td_bn0_g, td_bn0_b, 0);
    k_stats_part<<<64, 128>>>(p_h1, BQ*SP*KNN, p_part);
    k_stats_final<<<1, 128>>>(p_part, BQ*SP*KNN, p_m1, p_v1);
    k_maxpool<<<BQ*SP, 128>>>(td_bn1_g, td_bn1_b);
    k_gemm128<<<FD/32, 128, SM_GEMM>>>(w_kern, w_q, 0, p_wqc, 0, 0,0,0,0, 0);
    k_foldb<<<1, 128>>>(b_kern, w_q);
    k_gemm128<<<BQ*NP/32, 128, SM_GEMM>>>(p_feats, p_wqc, p_bqc, p_q, 0, 0,0,0,0, 0);
    k_gemm128<<<BQ*SP/32, 128, SM_GEMM>>>(p_newfeat, w_gkern, b_gkern, p_newx, 0, 0,0,0,0, 0);
    k_gemm128<<<BQ*SP/32, 128, SM_GEMM>>>(p_newx, w_k, 0, p_ktab, 0, 0,0,0,0, 0);
    k_gemm128<<<BQ*SP/32, 128, SM_GEMM>>>(p_newx, w_v, 0, p_vtab, 0, 0,0,0,0, 0);
    k_posenc_mma<<<296, 256, PM_SZ>>>(xyzp, pe_w1, pe_b1, pe_w2, pe_b2);
    k_att12_mma<<<148, 256, MA_SZ>>>(at_b1, at_b2, at_w1, at_w2);
    k_gemm128<<<BQ*NP/32, 128, SM_GEMM>>>(p_res, w_agg, b_agg, out, 4, 0,0,0,0, p_feats);
}

// round 15
// speedup vs baseline: 1.0627x; 1.0627x over previous
#include <cuda_runtime.h>
#include <cuda_bf16.h>
#include <stdint.h>
#include <math.h>

#define BQ 4
#define NP 8192
#define SP 512
#define KNN 16
#define FD 128
#define EPSV 1e-5f
typedef unsigned long long u64;

__device__ float g_feats[BQ*NP*FD];
__device__ float g_q[BQ*NP*FD];
__device__ int   g_fps[BQ*SP];
__device__ int   g_idx_dn[BQ*SP*KNN];
__device__ float g_new_xyz[BQ*SP*3];
__device__ float g_new_xyzp[BQ*SP*4];
__device__ float g_h0[BQ*SP*KNN*FD];
__device__ float g_h1[BQ*SP*KNN*FD];
__device__ float g_part[64*2*FD];
__device__ float g_m0[FD]; __device__ float g_v0[FD];
__device__ float g_m1[FD]; __device__ float g_v1[FD];
__device__ float g_newfeat[BQ*SP*FD];
__device__ float g_newx[BQ*SP*FD];
__device__ float g_ktab[BQ*SP*FD];
__device__ float g_vtab[BQ*SP*FD];
__device__ int   g_idx_up[BQ*NP*KNN];
__device__ float g_pe[67108864];
__device__ float g_res[BQ*NP*FD];
__device__ float g_wqc[FD*FD];
__device__ float g_bqc[FD];

// ---- f32x2 helpers ----
__device__ __forceinline__ u64 pk2(float a){ u64 r; asm("mov.b64 %0,{%1,%1};" : "=l"(r) : "f"(a)); return r; }
__device__ __forceinline__ void fma2(u64& d, u64 a, u64 b){ asm("fma.rn.f32x2 %0,%1,%2,%0;" : "+l"(d) : "l"(a), "l"(b)); }
__device__ __forceinline__ void upk(u64 v, float& lo, float& hi){ asm("mov.b64 {%0,%1},%2;" : "=f"(lo), "=f"(hi) : "l"(v)); }

__device__ __forceinline__ void gemm32_core(const float* __restrict__ Wsh, const float* __restrict__ Ash,
                                            int kg, int cg, u64 acc[8][2]){
    #pragma unroll
    for (int r=0;r<8;r++){ acc[r][0]=0ull; acc[r][1]=0ull; }
    const float* arow = Ash + (kg<<3)*FD;
    #pragma unroll 4
    for (int i=0;i<FD;i++){
        ulonglong2 w = *(const ulonglong2*)(Wsh + i*FD + (cg<<2));
        #pragma unroll
        for (int r=0;r<8;r++){
            u64 a2 = pk2(arow[r*FD + i]);
            fma2(acc[r][0], a2, w.x);
            fma2(acc[r][1], a2, w.y);
        }
    }
}

// ---- mma.sync helpers ----
__device__ __forceinline__ uint32_t smem_u32(const void* p){
    uint32_t a; asm("{ .reg .u64 t; cvta.to.shared.u64 t, %1; cvt.u32.u64 %0, t; }" : "=r"(a) : "l"(p)); return a;
}
#define LDSM4(r, addr) \
    asm volatile("ldmatrix.sync.aligned.m8n8.x4.shared.b16 {%0,%1,%2,%3}, [%4];" \
        : "=r"((r)[0]),"=r"((r)[1]),"=r"((r)[2]),"=r"((r)[3]) : "r"(addr))
#define MMA16816(cc, a, b0, b1) \
    asm volatile("mma.sync.aligned.m16n8k16.row.col.f32.bf16.bf16.f32 " \
        "{%0,%1,%2,%3},{%4,%5,%6,%7},{%8,%9},{%0,%1,%2,%3};" \
        : "+f"((cc)[0]),"+f"((cc)[1]),"+f"((cc)[2]),"+f"((cc)[3]) \
        : "r"((a)[0]),"r"((a)[1]),"r"((a)[2]),"r"((a)[3]),"r"(b0),"r"(b1))
__device__ __forceinline__ void bfsplit(float v, __nv_bfloat16& h, __nv_bfloat16& l){
    h=__float2bfloat16_rn(v); l=__float2bfloat16_rn(v-__bfloat162float(h));
}

__device__ __forceinline__ void wgemm(uint32_t aH, uint32_t aL, uint32_t bH, uint32_t bL,
                                      int wr, int wc, uint32_t offA, uint32_t offB, float c[32]){
    #pragma unroll
    for (int i=0;i<32;i++) c[i]=0.f;
    #pragma unroll
    for (int ks=0;ks<8;ks++){
        uint32_t k2 = ks*32;
        uint32_t ah[2][4], al[2][4], bh[2][4], bl[2][4];
        #pragma unroll
        for (int mt=0;mt<2;mt++){
            uint32_t ra = (uint32_t)(32*wr+16*mt)*272u + k2 + offA;
            LDSM4(ah[mt], aH + ra);
            LDSM4(al[mt], aL + ra);
        }
        #pragma unroll
        for (int np=0;np<2;np++){
            uint32_t rb = (uint32_t)(32*wc+16*np)*272u + k2 + offB;
            LDSM4(bh[np], bH + rb);
            LDSM4(bl[np], bL + rb);
        }
        #pragma unroll
        for (int mt=0;mt<2;mt++){
            #pragma unroll
            for (int nt=0;nt<4;nt++){
                float* cc = c + (mt*4+nt)*4;
                uint32_t b0h=bh[nt>>1][(nt&1)*2], b1h=bh[nt>>1][(nt&1)*2+1];
                uint32_t b0l=bl[nt>>1][(nt&1)*2], b1l=bl[nt>>1][(nt&1)*2+1];
                MMA16816(cc, ah[mt], b0h, b1h);
                MMA16816(cc, ah[mt], b0l, b1l);
                MMA16816(cc, al[mt], b0h, b1h);
            }
        }
    }
}

// ---------------- layernorm ----------------
__global__ void k_layernorm(const float* __restrict__ x, const float* __restrict__ g,
                            const float* __restrict__ b, float* __restrict__ out){
    int row = blockIdx.x, t = threadIdx.x;
    __shared__ float sh[8];
    float v = x[(size_t)row*FD + t];
    float s = v;
    #pragma unroll
    for (int o=16;o;o>>=1) s += __shfl_xor_sync(0xffffffffu, s, o);
    if ((t&31)==0) sh[t>>5]=s;
    __syncthreads();
    float mean = (sh[0]+sh[1]+sh[2]+sh[3]) * (1.0f/FD);
    float d = v - mean;
    float s2 = d*d;
    #pragma unroll
    for (int o=16;o;o>>=1) s2 += __shfl_xor_sync(0xffffffffu, s2, o);
    if ((t&31)==0) sh[4+(t>>5)]=s2;
    __syncthreads();
    float var = (sh[4]+sh[5]+sh[6]+sh[7]) * (1.0f/FD);
    out[(size_t)row*FD+t] = d * rsqrtf(var + EPSV) * g[t] + b[t];
}

// ---------------- FPS (R12 form) ----------------
__global__ void k_fps(const float* __restrict__ xyzp){
    extern __shared__ float sm[];
    float* xs = sm; float* ys = sm + NP; float* zs = sm + 2*NP;
    int b = blockIdx.x, t = threadIdx.x;
    float px[8], py[8], pz[8], md[8];
    #pragma unroll
    for (int j=0;j<8;j++){
        int i = t + j*1024;
        float4 p = ((const float4*)xyzp)[(size_t)b*NP + i];
        px[j]=p.x; py[j]=p.y; pz[j]=p.z; md[j]=1e10f;
        xs[i]=p.x; ys[i]=p.y; zs[i]=p.z;
    }
    __shared__ u64 warpbest[32];
    __shared__ int s_last;
    if (t==0){ g_fps[b*SP]=0; s_last=0; }
    __syncthreads();
    int last = 0;
    for (int s=1;s<SP;s++){
        float lx=xs[last], ly=ys[last], lz=zs[last];
        u64 best=0;
        #pragma unroll
        for (int j=0;j<8;j++){
            float dx=px[j]-lx, dy=py[j]-ly, dz=pz[j]-lz;
            float d = dx*dx+dy*dy+dz*dz;
            md[j] = fminf(md[j], d);
            u64 key = ((u64)__float_as_uint(md[j])<<32) | (unsigned)(NP-1 - (t + j*1024));
            best = key > best ? key : best;
        }
        #pragma unroll
        for (int o=16;o;o>>=1){
            u64 oth = __shfl_xor_sync(0xffffffffu, best, o);
            best = oth > best ? oth : best;
        }
        if ((t&31)==0) warpbest[t>>5]=best;
        __syncthreads();
        if (t<32){
            u64 bb = warpbest[t];
            #pragma unroll
            for (int o=16;o;o>>=1){
                u64 oth = __shfl_xor_sync(0xffffffffu, bb, o);
                bb = oth > bb ? oth : bb;
            }
            if (t==0){ s_last = NP-1 - (int)(bb & 0xffffffffu); g_fps[b*SP+s]=s_last; }
        }
        __syncthreads();
        last = s_last;
    }
}

// ---------------- knn_dn (R12 form) ----------------
__global__ void k_knn_dn(const float* __restrict__ xyzp){
    extern __shared__ float sm[];
    float* xs = sm; float* ys = sm+NP; float* zs = sm+2*NP;
    int b = blockIdx.x >> 5, blk = blockIdx.x & 31;
    int t = threadIdx.x, w = t>>5, lane = t&31;
    for (int i=t;i<NP;i+=256){
        float4 p = ((const float4*)xyzp)[(size_t)b*NP + i];
        xs[i]=p.x; ys[i]=p.y; zs[i]=p.z;
    }
    __syncthreads();
    for (int qi=0; qi<2; qi++){
        int s = blk*16 + w*2 + qi;
        int qidx = g_fps[b*SP+s];
        float qx=xs[qidx], qy=ys[qidx], qz=zs[qidx];
        if (lane==0){
            g_new_xyz[(b*SP+s)*3+0]=qx; g_new_xyz[(b*SP+s)*3+1]=qy; g_new_xyz[(b*SP+s)*3+2]=qz;
        }
        u64 kk[16];
        #pragma unroll
        for (int j=0;j<16;j++) kk[j]=~0ull;
        for (int r=lane; r<NP; r+=32){
            float dx=xs[r]-qx, dy=ys[r]-qy, dz=zs[r]-qz;
            float d = dx*dx+dy*dy+dz*dz;
            u64 key = ((u64)__float_as_uint(d)<<32) | (unsigned)r;
            if (key < kk[15]){
                #pragma unroll
                for (int j=0;j<16;j++){
                    u64 lo = kk[j] < key ? kk[j] : key;
                    u64 hi = kk[j] < key ? key : kk[j];
                    kk[j]=lo; key=hi;
                }
            }
        }
        u64 prev = 0;
        for (int r=0;r<16;r++){
            u64 thr = (r==0) ? 0ull : prev + 1ull;
            u64 loc = ~0ull;
            #pragma unroll
            for (int j=0;j<16;j++){ u64 v = kk[j]; if (v >= thr && v < loc) loc = v; }
            #pragma unroll
            for (int o=16;o;o>>=1){
                u64 oth = __shfl_xor_sync(0xffffffffu, loc, o);
                loc = oth < loc ? oth : loc;
            }
            prev = loc;
            if (lane==0){
                int id = (int)(loc & 0xffffffffu);
                g_idx_dn[(b*SP+s)*KNN + r] = id;
                if (r==0) ((float4*)g_new_xyzp)[b*SP+s] = ((const float4*)xyzp)[(size_t)b*NP + id];
            }
        }
    }
}

// ---------------- knn_up (R12 form) ----------------
__global__ void k_knn_up(const float* __restrict__ xyzp){
    __shared__ float rx[SP], ry[SP], rz[SP];
    int t=threadIdx.x, w=t>>5, lane=t&31;
    int b = blockIdx.x >> 10;
    int n = (blockIdx.x & 1023)*8 + w;
    for (int i=t;i<SP;i+=256){
        rx[i]=g_new_xyz[(i+b*SP)*3+0]; ry[i]=g_new_xyz[(i+b*SP)*3+1]; rz[i]=g_new_xyz[(i+b*SP)*3+2];
    }
    __syncthreads();
    float4 qp = ((const float4*)xyzp)[(size_t)b*NP + n];
    u64 kk[16];
    #pragma unroll
    for (int j=0;j<16;j++){
        int r = lane + 32*j;
        float dx=rx[r]-qp.x, dy=ry[r]-qp.y, dz=rz[r]-qp.z;
        kk[j] = ((u64)__float_as_uint(dx*dx+dy*dy+dz*dz)<<32) | (unsigned)r;
    }
    u64 prev = 0;
    for (int r=0;r<16;r++){
        u64 thr = (r==0) ? 0ull : prev + 1ull;
        u64 loc = ~0ull;
        #pragma unroll
        for (int j=0;j<16;j++){ u64 v = kk[j]; if (v >= thr && v < loc) loc = v; }
        #pragma unroll
        for (int o=16;o;o>>=1){
            u64 oth = __shfl_xor_sync(0xffffffffu, loc, o);
            loc = oth < loc ? oth : loc;
        }
        prev = loc;
        if (lane==0) g_idx_up[((size_t)b*NP+n)*KNN + r] = (int)(loc & 0xffffffffu);
    }
}

// ---------------- h0 ----------------
__global__ __launch_bounds__(128) void k_h032(const float* __restrict__ xyzp,
                                              const float* __restrict__ tw0,
                                              const float* __restrict__ tb0){
    extern __shared__ float sm[];
    float* Wsh = sm;
    float* Ash = sm + 16384;
    __shared__ float w3[3*FD];
    __shared__ float gx[32][3];
    __shared__ int idxs[32];
    int t = threadIdx.x, bs = blockIdx.x;
    int s0 = bs*2, b = s0 >> 9;
    for (int i=t;i<16384;i+=128) Wsh[i] = tw0[384 + i];
    w3[t]=tw0[t]; w3[128+t]=tw0[128+t]; w3[256+t]=tw0[256+t];
    if (t<32){
        int s = s0 + (t>>4);
        int id = g_idx_dn[s*KNN + (t&15)];
        idxs[t]=id;
        gx[t][0]=xyzp[((size_t)b*NP+id)*4+0]-g_new_xyz[s*3+0];
        gx[t][1]=xyzp[((size_t)b*NP+id)*4+1]-g_new_xyz[s*3+1];
        gx[t][2]=xyzp[((size_t)b*NP+id)*4+2]-g_new_xyz[s*3+2];
    }
    __syncthreads();
    #pragma unroll
    for (int k=0;k<32;k++) Ash[k*FD+t] = g_feats[((size_t)b*NP+idxs[k])*FD + t];
    __syncthreads();
    int kg=t>>5, cg=t&31;
    u64 acc[8][2];
    gemm32_core(Wsh, Ash, kg, cg, acc);
    float4 bv = ((const float4*)tb0)[cg];
    #pragma unroll
    for (int r=0;r<8;r++){
        int row = (kg<<3)+r;
        float g0=gx[row][0], g1=gx[row][1], g2=gx[row][2];
        float c0,c1,c2,c3;
        upk(acc[r][0],c0,c1); upk(acc[r][1],c2,c3);
        int cb=cg<<2;
        c0 += bv.x + g0*w3[cb+0] + g1*w3[128+cb+0] + g2*w3[256+cb+0];
        c1 += bv.y + g0*w3[cb+1] + g1*w3[128+cb+1] + g2*w3[256+cb+1];
        c2 += bv.z + g0*w3[cb+2] + g1*w3[128+cb+2] + g2*w3[256+cb+2];
        c3 += bv.w + g0*w3[cb+3] + g1*w3[128+cb+3] + g2*w3[256+cb+3];
        ((float4*)g_h0)[((size_t)bs*32 + row)*32 + cg] = make_float4(c0,c1,c2,c3);
    }
}

// ---------------- stats ----------------
__global__ void k_stats_part(const float* __restrict__ X, int nrows, float* __restrict__ part){
    int t=threadIdx.x, blk=blockIdx.x;
    int chunk = nrows/64;
    float s=0.f, s2=0.f;
    for (int r=0;r<chunk;r++){
        float v = X[((size_t)(blk*chunk+r))*FD + t];
        s += v; s2 += v*v;
    }
    part[blk*2*FD + t] = s;
    part[blk*2*FD + FD + t] = s2;
}
__global__ void k_stats_final(const float* __restrict__ part, int nrows,
                              float* __restrict__ mean, float* __restrict__ var){
    int t=threadIdx.x;
    float s=0.f, s2=0.f;
    for (int i=0;i<64;i++){ s += part[i*2*FD+t]; s2 += part[i*2*FD+FD+t]; }
    float m = s/(float)nrows;
    mean[t]=m;
    var[t]=s2/(float)nrows - m*m;
}

// ---------------- gemm128 (f32x2, kept for small/BN GEMMs) ----------------
__global__ __launch_bounds__(128) void k_gemm128(
        const float* __restrict__ A, const float* __restrict__ W,
        const float* __restrict__ bias, float* __restrict__ C, int flags,
        const float* __restrict__ bnm, const float* __restrict__ bnv,
        const float* __restrict__ bng, const float* __restrict__ bnb,
        const float* __restrict__ addsrc){
    extern __shared__ float sm[];
    float* Wsh = sm; float* Ash = sm + 16384;
    int t=threadIdx.x;
    size_t row0 = (size_t)blockIdx.x*32;
    for (int i=t;i<4096;i+=128) ((float4*)Wsh)[i]=((const float4*)W)[i];
    float bm=0.f, brv=1.f, bg=1.f, bb=0.f;
    if (flags&2){ bm=bnm[t]; brv=rsqrtf(bnv[t]+EPSV); bg=bng[t]; bb=bnb[t]; }
    #pragma unroll
    for (int k=0;k<32;k++){
        float v = A[(row0+k)*FD + t];
        if (flags&2) v = fmaxf((v-bm)*brv*bg + bb, 0.f);
        Ash[k*FD+t]=v;
    }
    __syncthreads();
    int kg=t>>5, cg=t&31;
    u64 acc[8][2];
    gemm32_core(Wsh, Ash, kg, cg, acc);
    float4 bv = bias ? ((const float4*)bias)[cg] : make_float4(0.f,0.f,0.f,0.f);
    #pragma unroll
    for (int r=0;r<8;r++){
        size_t row = row0 + (kg<<3) + r;
        float c0,c1,c2,c3;
        upk(acc[r][0],c0,c1); upk(acc[r][1],c2,c3);
        float4 o = make_float4(c0+bv.x, c1+bv.y, c2+bv.z, c3+bv.w);
        if (flags&1){ o.x=fmaxf(o.x,0.f); o.y=fmaxf(o.y,0.f); o.z=fmaxf(o.z,0.f); o.w=fmaxf(o.w,0.f); }
        if (flags&4){
            float4 ad = ((const float4*)addsrc)[row*32 + cg];
            o.x+=ad.x; o.y+=ad.y; o.z+=ad.z; o.w+=ad.w;
        }
        ((float4*)C)[row*32 + cg] = o;
    }
}

// ---------------- maxpool / foldb ----------------
__global__ void k_maxpool(const float* __restrict__ bg, const float* __restrict__ bb){
    int bs = blockIdx.x, t = threadIdx.x;
    float m = g_m1[t], rv = rsqrtf(g_v1[t]+EPSV), ga=bg[t], be=bb[t];
    float best = -1e30f;
    #pragma unroll
    for (int k=0;k<KNN;k++){
        float v = g_h1[((size_t)bs*KNN+k)*FD + t];
        v = fmaxf((v-m)*rv*ga + be, 0.f);
        best = fmaxf(best, v);
    }
    g_newfeat[(size_t)bs*FD+t] = best;
}
__global__ void k_foldb(const float* __restrict__ bk, const float* __restrict__ wq){
    int t = threadIdx.x;
    float s = 0.f;
    for (int i=0;i<FD;i++) s += bk[i]*wq[i*FD+t];
    g_bqc[t] = s;
}

// ================= generic 64-row linear via mma.sync split-bf16 =================
// smem: bias 0(512), A_HI 1024(17408), A_LO 18432(17408), WH 35840(34816), WL 70656(34816)
// total 105472 -> 2 CTAs/SM
#define LM_AHI 1024
#define LM_ALO 18432
#define LM_WH  35840
#define LM_WL  70656
#define LM_SZ  105472
__global__ __launch_bounds__(256,2) void k_lin_mma(
        const float* __restrict__ A, const float* __restrict__ W,
        const float* __restrict__ bias, float* __restrict__ C,
        const float* __restrict__ addsrc){
    extern __shared__ __align__(1024) char smem[];
    uint32_t sb = smem_u32(smem);
    int t=threadIdx.x, wid=t>>5, lane=t&31;
    float* bs=(float*)(smem+0);
    if (t<128) bs[t]=bias[t];
    for (int j=t;j<16384;j+=256){
        int k=j>>7, n=j&127;
        uint32_t off=(uint32_t)n*272u + (uint32_t)k*2u;
        __nv_bfloat16 h,l; bfsplit(W[k*128+n],h,l);
        *(__nv_bfloat16*)(smem+LM_WH+off)=h;
        *(__nv_bfloat16*)(smem+LM_WL+off)=l;
    }
    int c=t&127, rh=t>>7;
    size_t row0=(size_t)blockIdx.x*64;
    #pragma unroll 4
    for (int rr=0;rr<32;rr++){
        int r=rh*32+rr;
        float v=A[(row0+r)*FD+c];
        __nv_bfloat16 h,l; bfsplit(v,h,l);
        uint32_t off=(uint32_t)r*272u + (uint32_t)c*2u;
        *(__nv_bfloat16*)(smem+LM_AHI+off)=h;
        *(__nv_bfloat16*)(smem+LM_ALO+off)=l;
    }
    __syncthreads();
    int wr=wid&1, wc=wid>>1;
    int g=lane>>2, tig=lane&3, r8=lane&7, sel=lane>>3;
    uint32_t offA=(uint32_t)(r8+((sel&1)<<3))*272u + (uint32_t)((sel>>1)<<4);
    uint32_t offB=(uint32_t)(r8+((sel>>1)<<3))*272u + (uint32_t)((sel&1)<<4);
    float cfr[32];
    wgemm(sb+LM_AHI, sb+LM_ALO, sb+LM_WH, sb+LM_WL, wr, wc, offA, offB, cfr);
    #pragma unroll
    for (int mt=0;mt<2;mt++){
        #pragma unroll
        for (int nt=0;nt<4;nt++){
            float* cc=cfr+(mt*4+nt)*4;
            int rf=32*wr+16*mt+g;
            int col0=32*wc+8*nt+2*tig;
            float bx=bs[col0], by=bs[col0+1];
            float2 o0=make_float2(cc[0]+bx, cc[1]+by);
            float2 o1=make_float2(cc[2]+bx, cc[3]+by);
            if (addsrc){
                float2 a0=*(const float2*)(addsrc+(row0+rf)*FD+col0);
                float2 a1=*(const float2*)(addsrc+(row0+rf+8)*FD+col0);
                o0.x+=a0.x; o0.y+=a0.y; o1.x+=a1.x; o1.y+=a1.y;
            }
            *(float2*)(C+(row0+rf)*FD+col0)  =o0;
            *(float2*)(C+(row0+rf+8)*FD+col0)=o1;
        }
    }
}

// ================= posenc via mma.sync split-bf16 (validated R12) =================
#define PM_PD  0
#define PM_B2  1024
#define PM_AHI 1536
#define PM_ALO 18944
#define PM_WH  36352
#define PM_WL  71168
#define PM_SZ  105984
__global__ __launch_bounds__(256,2) void k_posenc_mma(
        const float* __restrict__ xyzp,
        const float* __restrict__ pe_w1, const float* __restrict__ pe_b1,
        const float* __restrict__ pe_w2, const float* __restrict__ pe_b2){
    extern __shared__ __align__(1024) char smem[];
    uint32_t sb = smem_u32(smem);
    int t=threadIdx.x, wid=t>>5, lane=t&31;
    float* pd =(float*)(smem+PM_PD);
    float* b2s=(float*)(smem+PM_B2);
    if (t<128) b2s[t]=pe_b2[t];
    for (int j=t;j<16384;j+=256){
        int k=j>>7, n=j&127;
        uint32_t off=(uint32_t)n*272u + (uint32_t)k*2u;
        __nv_bfloat16 h,l; bfsplit(pe_w2[k*128+n],h,l);
        *(__nv_bfloat16*)(smem+PM_WH+off)=h;
        *(__nv_bfloat16*)(smem+PM_WL+off)=l;
    }
    int c=t&127, rh=t>>7;
    float w0=pe_w1[c], w1=pe_w1[FD+c], w2=pe_w1[2*FD+c], w3=pe_w1[3*FD+c], bb1=pe_b1[c];
    int wr=wid&1, wc=wid>>1;
    int g=lane>>2, tig=lane&3, r8=lane&7, sel=lane>>3;
    uint32_t offA=(uint32_t)(r8+((sel&1)<<3))*272u + (uint32_t)((sel>>1)<<4);
    uint32_t offB=(uint32_t)(r8+((sel>>1)<<3))*272u + (uint32_t)((sel&1)<<4);
    __syncthreads();
    for (int tp=blockIdx.x; tp<BQ*NP/4; tp+=gridDim.x){
        int bn0=tp*4, b=bn0>>13;
        __syncthreads();
        if (t<64){
            int k=t, bn=bn0+(k>>4);
            int id=g_idx_up[(size_t)bn*KNN+(k&15)];
            float4 qp=((const float4*)xyzp)[bn];
            float4 np=((const float4*)g_new_xyzp)[b*SP+id];
            pd[k*4+0]=qp.x-np.x; pd[k*4+1]=qp.y-np.y; pd[k*4+2]=qp.z-np.z; pd[k*4+3]=qp.w-np.w;
        }
        __syncthreads();
        #pragma unroll 4
        for (int rr=0;rr<32;rr++){
            int r=rh*32+rr;
            float v=fmaxf(bb1 + pd[r*4+0]*w0 + pd[r*4+1]*w1 + pd[r*4+2]*w2 + pd[r*4+3]*w3, 0.f);
            __nv_bfloat16 h,l; bfsplit(v,h,l);
            uint32_t off=(uint32_t)r*272u + (uint32_t)c*2u;
            *(__nv_bfloat16*)(smem+PM_AHI+off)=h;
            *(__nv_bfloat16*)(smem+PM_ALO+off)=l;
        }
        __syncthreads();
        float cfr[32];
        wgemm(sb+PM_AHI, sb+PM_ALO, sb+PM_WH, sb+PM_WL, wr, wc, offA, offB, cfr);
        size_t base=(size_t)bn0*16;
        #pragma unroll
        for (int mt=0;mt<2;mt++){
            #pragma unroll
            for (int nt=0;nt<4;nt++){
                float* cc=cfr+(mt*4+nt)*4;
                int row0=32*wr+16*mt+g;
                int col0=32*wc+8*nt+2*tig;
                float bx=b2s[col0], by=b2s[col0+1];
                *(float2*)(g_pe+(base+row0)*FD+col0)   = make_float2(cc[0]+bx, cc[1]+by);
                *(float2*)(g_pe+(base+row0+8)*FD+col0) = make_float2(cc[2]+bx, cc[3]+by);
            }
        }
    }
}

// ================= att12 via mma.sync split-bf16 (validated R12) =================
#define MA_AHI 1280
#define MA_ALO 18688
#define MA_W1H 36096
#define MA_W1L 70912
#define MA_W2H 105728
#define MA_W2L 140544
#define MA_SZ  175360
__global__ __launch_bounds__(256,1) void k_att12_mma(
        const float* __restrict__ at_b1, const float* __restrict__ at_b2,
        const float* __restrict__ at_w1, const float* __restrict__ at_w2){
    extern __shared__ __align__(1024) char smem[];
    uint32_t sb = smem_u32(smem);
    int t=threadIdx.x, wid=t>>5, lane=t&31;
    int*   sidx=(int*)(smem+0);
    float* b1s =(float*)(smem+256);
    float* b2s =(float*)(smem+768);
    float* sfb =(float*)(smem+MA_AHI);
    if (t<128){ b1s[t]=at_b1[t]; b2s[t]=at_b2[t]; }
    for (int j=t;j<16384;j+=256){
        int k=j>>7, n=j&127;
        uint32_t off=(uint32_t)n*272u + (uint32_t)k*2u;
        __nv_bfloat16 h,l;
        bfsplit(at_w1[k*128+n],h,l);
        *(__nv_bfloat16*)(smem+MA_W1H+off)=h; *(__nv_bfloat16*)(smem+MA_W1L+off)=l;
        bfsplit(at_w2[k*128+n],h,l);
        *(__nv_bfloat16*)(smem+MA_W2H+off)=h; *(__nv_bfloat16*)(smem+MA_W2L+off)=l;
    }
    int c=t&127, rh=t>>7;
    int wr=wid&1, wc=wid>>1;
    int g=lane>>2, tig=lane&3, r8=lane&7, sel=lane>>3;
    uint32_t offA=(uint32_t)(r8+((sel&1)<<3))*272u + (uint32_t)((sel>>1)<<4);
    uint32_t offB=(uint32_t)(r8+((sel>>1)<<3))*272u + (uint32_t)((sel&1)<<4);
    const float inv = 0.08838834764831845f;
    __syncthreads();
    for (int tp=blockIdx.x; tp<BQ*NP/4; tp+=gridDim.x){
        int bn0=tp*4, b=bn0>>13;
        __syncthreads();
        if (t<64) sidx[t]=g_idx_up[(size_t)(bn0+(t>>4))*KNN + (t&15)];
        __syncthreads();
        {
            float qs[4];
            #pragma unroll
            for (int p=0;p<4;p++) qs[p]=g_q[(size_t)(bn0+p)*FD+c];
            #pragma unroll 4
            for (int rr=0;rr<32;rr++){
                int r=rh*32+rr;
                int id=sidx[r];
                float v=qs[r>>4]-g_ktab[(size_t)(b*SP+id)*FD+c]+g_pe[((size_t)bn0*16+r)*FD+c];
                __nv_bfloat16 h,l; bfsplit(v,h,l);
                uint32_t off=(uint32_t)r*272u + (uint32_t)c*2u;
                *(__nv_bfloat16*)(smem+MA_AHI+off)=h;
                *(__nv_bfloat16*)(smem+MA_ALO+off)=l;
            }
        }
        __syncthreads();
        float cfr[32];
        wgemm(sb+MA_AHI, sb+MA_ALO, sb+MA_W1H, sb+MA_W1L, wr, wc, offA, offB, cfr);
        __syncthreads();
        #pragma unroll
        for (int mt=0;mt<2;mt++){
            #pragma unroll
            for (int nt=0;nt<4;nt++){
                float* cc=cfr+(mt*4+nt)*4;
                int row0=32*wr+16*mt+g;
                int col0=32*wc+8*nt+2*tig;
                float bvx=b1s[col0], bvy=b1s[col0+1];
                float v0=fmaxf(cc[0]+bvx,0.f), v1=fmaxf(cc[1]+bvy,0.f);
                float v2=fmaxf(cc[2]+bvx,0.f), v3=fmaxf(cc[3]+bvy,0.f);
                __nv_bfloat16 h0,l0,h1,l1;
                uint32_t o0=(uint32_t)row0*272u+(uint32_t)col0*2u;
                uint32_t o1=(uint32_t)(row0+8)*272u+(uint32_t)col0*2u;
                __nv_bfloat162 hp,lp;
                bfsplit(v0,h0,l0); bfsplit(v1,h1,l1);
                hp.x=h0; hp.y=h1; lp.x=l0; lp.y=l1;
                *(__nv_bfloat162*)(smem+MA_AHI+o0)=hp; *(__nv_bfloat162*)(smem+MA_ALO+o0)=lp;
                bfsplit(v2,h0,l0); bfsplit(v3,h1,l1);
                hp.x=h0; hp.y=h1; lp.x=l0; lp.y=l1;
                *(__nv_bfloat162*)(smem+MA_AHI+o1)=hp; *(__nv_bfloat162*)(smem+MA_ALO+o1)=lp;
            }
        }
        __syncthreads();
        wgemm(sb+MA_AHI, sb+MA_ALO, sb+MA_W2H, sb+MA_W2L, wr, wc, offA, offB, cfr);
        __syncthreads();
        #pragma unroll
        for (int mt=0;mt<2;mt++){
            #pragma unroll
            for (int nt=0;nt<4;nt++){
                float* cc=cfr+(mt*4+nt)*4;
                int row0=32*wr+16*mt+g;
                int col0=32*wc+8*nt+2*tig;
                sfb[col0*66+row0]      =cc[0]+b2s[col0];
                sfb[(col0+1)*66+row0]  =cc[1]+b2s[col0+1];
                sfb[col0*66+row0+8]    =cc[2]+b2s[col0];
                sfb[(col0+1)*66+row0+8]=cc[3]+b2s[col0+1];
            }
        }
        __syncthreads();
        #pragma unroll
        for (int j=0;j<2;j++){
            int item=t+256*j;
            int p=item>>7, ch=item&127;
            float s[16], mx=-1e30f;
            #pragma unroll
            for (int k=0;k<16;k++){ s[k]=sfb[ch*66+p*16+k]*inv; mx=fmaxf(mx,s[k]); }
            float den=0.f;
            #pragma unroll
            for (int k=0;k<16;k++){ s[k]=expf(s[k]-mx); den+=s[k]; }
            float rden=1.f/den, r=0.f;
            #pragma unroll
            for (int k=0;k<16;k++){
                int id=sidx[p*16+k];
                float v=g_vtab[(size_t)(b*SP+id)*FD+ch] + g_pe[((size_t)bn0*16+p*16+k)*FD+ch];
                r += s[k]*rden*v;
            }
            g_res[(size_t)(bn0+p)*FD+ch]=r;
        }
    }
}

extern "C" void kernel_launch(void* const* d_in, const int* in_sizes, int n_in,
                              void* d_out, int out_size){
    const float* xyzp     = (const float*)d_in[0];
    const float* features = (const float*)d_in[1];
    const float* ln_g     = (const float*)d_in[2];
    const float* ln_b     = (const float*)d_in[3];
    const float* td_w0    = (const float*)d_in[4];
    const float* td_b0    = (const float*)d_in[5];
    const float* td_bn0_g = (const float*)d_in[6];
    const float* td_bn0_b = (const float*)d_in[7];
    const float* td_w1    = (const float*)d_in[8];
    const float* td_b1    = (const float*)d_in[9];
    const float* td_bn1_g = (const float*)d_in[10];
    const float* td_bn1_b = (const float*)d_in[11];
    const float* w_kern   = (const float*)d_in[12];
    const float* b_kern   = (const float*)d_in[13];
    const float* w_gkern  = (const float*)d_in[14];
    const float* b_gkern  = (const float*)d_in[15];
    const float* w_agg    = (const float*)d_in[16];
    const float* b_agg    = (const float*)d_in[17];
    const float* w_q      = (const float*)d_in[18];
    const float* w_k      = (const float*)d_in[19];
    const float* w_v      = (const float*)d_in[20];
    const float* pe_w1    = (const float*)d_in[21];
    const float* pe_b1    = (const float*)d_in[22];
    const float* pe_w2    = (const float*)d_in[23];
    const float* pe_b2    = (const float*)d_in[24];
    const float* at_w1    = (const float*)d_in[25];
    const float* at_b1    = (const float*)d_in[26];
    const float* at_w2    = (const float*)d_in[27];
    const float* at_b2    = (const float*)d_in[28];
    float* out = (float*)d_out;

    float *p_feats,*p_q,*p_h0,*p_h1,*p_part,*p_m0,*p_v0,*p_m1,*p_v1;
    float *p_newfeat,*p_newx,*p_ktab,*p_vtab,*p_res,*p_wqc,*p_bqc;
    cudaGetSymbolAddress((void**)&p_feats,   g_feats);
    cudaGetSymbolAddress((void**)&p_q,       g_q);
    cudaGetSymbolAddress((void**)&p_h0,      g_h0);
    cudaGetSymbolAddress((void**)&p_h1,      g_h1);
    cudaGetSymbolAddress((void**)&p_part,    g_part);
    cudaGetSymbolAddress((void**)&p_m0,      g_m0);
    cudaGetSymbolAddress((void**)&p_v0,      g_v0);
    cudaGetSymbolAddress((void**)&p_m1,      g_m1);
    cudaGetSymbolAddress((void**)&p_v1,      g_v1);
    cudaGetSymbolAddress((void**)&p_newfeat, g_newfeat);
    cudaGetSymbolAddress((void**)&p_newx,    g_newx);
    cudaGetSymbolAddress((void**)&p_ktab,    g_ktab);
    cudaGetSymbolAddress((void**)&p_vtab,    g_vtab);
    cudaGetSymbolAddress((void**)&p_res,     g_res);
    cudaGetSymbolAddress((void**)&p_wqc,     g_wqc);
    cudaGetSymbolAddress((void**)&p_bqc,     g_bqc);

    const int SM_PTS  = 3*NP*4;
    const int SM_GEMM = (16384 + 4096)*4;
    cudaFuncSetAttribute(k_fps,        cudaFuncAttributeMaxDynamicSharedMemorySize, SM_PTS);
    cudaFuncSetAttribute(k_knn_dn,     cudaFuncAttributeMaxDynamicSharedMemorySize, SM_PTS);
    cudaFuncSetAttribute(k_h032,       cudaFuncAttributeMaxDynamicSharedMemorySize, SM_GEMM);
    cudaFuncSetAttribute(k_gemm128,    cudaFuncAttributeMaxDynamicSharedMemorySize, SM_GEMM);
    cudaFuncSetAttribute(k_lin_mma,    cudaFuncAttributeMaxDynamicSharedMemorySize, LM_SZ);
    cudaFuncSetAttribute(k_posenc_mma, cudaFuncAttributeMaxDynamicSharedMemorySize, PM_SZ);
    cudaFuncSetAttribute(k_att12_mma,  cudaFuncAttributeMaxDynamicSharedMemorySize, MA_SZ);

    k_layernorm<<<BQ*NP, 128>>>(features, ln_g, ln_b, p_feats);
    k_fps<<<BQ, 1024, SM_PTS>>>(xyzp);
    k_knn_dn<<<BQ*32, 256, SM_PTS>>>(xyzp);
    k_knn_up<<<BQ*1024, 256>>>(xyzp);
    k_h032<<<BQ*SP/2, 128, SM_GEMM>>>(xyzp, td_w0, td_b0);
    k_stats_part<<<64, 128>>>(p_h0, BQ*SP*KNN, p_part);
    k_stats_final<<<1, 128>>>(p_part, BQ*SP*KNN, p_m0, p_v0);
    k_gemm128<<<BQ*SP*KNN/32, 128, SM_GEMM>>>(p_h0, td_w1, td_b1, p_h1, 2,
                                              p_m0, p_v0, td_bn0_g, td_bn0_b, 0);
    k_stats_part<<<64, 128>>>(p_h1, BQ*SP*KNN, p_part);
    k_stats_final<<<1, 128>>>(p_part, BQ*SP*KNN, p_m1, p_v1);
    k_maxpool<<<BQ*SP, 128>>>(td_bn1_g, td_bn1_b);
    k_gemm128<<<FD/32, 128, SM_GEMM>>>(w_kern, w_q, 0, p_wqc, 0, 0,0,0,0, 0);
    k_foldb<<<1, 128>>>(b_kern, w_q);
    k_lin_mma<<<BQ*NP/64, 256, LM_SZ>>>(p_feats, p_wqc, p_bqc, p_q, 0);
    k_gemm128<<<BQ*SP/32, 128, SM_GEMM>>>(p_newfeat, w_gkern, b_gkern, p_newx, 0, 0,0,0,0, 0);
    k_gemm128<<<BQ*SP/32, 128, SM_GEMM>>>(p_newx, w_k, 0, p_ktab, 0, 0,0,0,0, 0);
    k_gemm128<<<BQ*SP/32, 128, SM_GEMM>>>(p_newx, w_v, 0, p_vtab, 0, 0,0,0,0, 0);
    k_posenc_mma<<<296, 256, PM_SZ>>>(xyzp, pe_w1, pe_b1, pe_w2, pe_b2);
    k_att12_mma<<<148, 256, MA_SZ>>>(at_b1, at_b2, at_w1, at_w2);
    k_lin_mma<<<BQ*NP/64, 256, LM_SZ>>>(p_res, w_agg, b_agg, out, p_feats);
}